// round 4
// baseline (speedup 1.0000x reference)
#include <cuda_runtime.h>
#include <math.h>

#define IN_DIM   8192
#define OUT_DIM  8192
#define BATCH    8192
#define NBUF     4            // 4 x 32 KB row buffers, 3 tiles in flight
#define THREADS  1024
#define COLS_PT  (OUT_DIM / THREADS)   // 8 columns per thread
#define GRID     152          // one persistent CTA per GB300 SM

// GATE_COEFFS, 16 x 4
__constant__ float GC[16][4] = {
    {0, 0, 0, 0}, {0, 0, 0, 1}, {0, 1, 0, -1}, {0, 1, 0, 0},
    {0, 0, 1, -1}, {0, 0, 1, 0}, {0, 1, 1, -2}, {0, 1, 1, -1},
    {1, -1, -1, 1}, {1, -1, -1, 2}, {1, 0, -1, 0}, {1, 0, -1, 1},
    {1, -1, 0, 0}, {1, -1, 0, 1}, {1, 0, 0, -1}, {1, 0, 0, 0}
};

extern __shared__ float smem[];   // NBUF * IN_DIM floats = 128 KB

__device__ __forceinline__ void stage_tile(int buf, int tile,
                                           const float* __restrict__ x) {
    // Copy one x row (32 KB) into smem buffer via cp.async (16B chunks).
    const char* src = (const char*)(x + (size_t)tile * IN_DIM);
    unsigned dst = (unsigned)__cvta_generic_to_shared(smem + buf * IN_DIM);
    constexpr int CP = IN_DIM * 4 / 16 / THREADS;   // 2
#pragma unroll
    for (int i = 0; i < CP; i++) {
        int off = (threadIdx.x + i * THREADS) * 16;
        asm volatile("cp.async.cg.shared.global [%0], [%1], 16;\n"
                     :: "r"(dst + off), "l"(src + off));
    }
}

__global__ void __launch_bounds__(THREADS, 1)
logic_dense_kernel(const float* __restrict__ x,
                   const float* __restrict__ weight,
                   const int* __restrict__ idx_a,
                   const int* __restrict__ idx_b,
                   float* __restrict__ out) {
    constexpr int NT = BATCH;          // one row per tile
    const int t0 = blockIdx.x;

    // Kick off the first 3 tile copies immediately so DMA overlaps the
    // per-thread softmax prologue below.
#pragma unroll
    for (int d = 0; d < NBUF - 1; d++) {
        int t = t0 + d * GRID;
        if (t < NT) stage_tile(d, t, x);
        asm volatile("cp.async.commit_group;\n");
    }

    // Prologue: this thread's 8 columns' softmax -> gate coefficients + idx,
    // cached in registers for the whole run.
    float4   c[COLS_PT];
    unsigned id[COLS_PT];
#pragma unroll
    for (int u = 0; u < COLS_PT; u++) {
        const int j = threadIdx.x + u * THREADS;
        const float4* wr = reinterpret_cast<const float4*>(weight + j * 16);
        float v[16];
#pragma unroll
        for (int q = 0; q < 4; q++) {
            float4 w4 = wr[q];
            v[q * 4 + 0] = w4.x; v[q * 4 + 1] = w4.y;
            v[q * 4 + 2] = w4.z; v[q * 4 + 3] = w4.w;
        }
        float m = v[0];
#pragma unroll
        for (int q = 1; q < 16; q++) m = fmaxf(m, v[q]);
        float s = 0.0f;
#pragma unroll
        for (int q = 0; q < 16; q++) { v[q] = expf(v[q] - m); s += v[q]; }
        const float inv = 1.0f / s;
        float c0 = 0.f, c1 = 0.f, c2 = 0.f, c3 = 0.f;
#pragma unroll
        for (int q = 0; q < 16; q++) {
            const float w = v[q] * inv;
            c0 = fmaf(w, GC[q][0], c0);
            c1 = fmaf(w, GC[q][1], c1);
            c2 = fmaf(w, GC[q][2], c2);
            c3 = fmaf(w, GC[q][3], c3);
        }
        c[u]  = make_float4(c0, c1, c2, c3);
        id[u] = (unsigned)idx_a[j] | ((unsigned)idx_b[j] << 13);
    }

    int k = 0;
    for (int t = t0; t < NT; t += GRID, k++) {
        const int ts = t + (NBUF - 1) * GRID;
        if (ts < NT) stage_tile((k + NBUF - 1) & (NBUF - 1), ts, x);
        asm volatile("cp.async.commit_group;\n");
        asm volatile("cp.async.wait_group %0;\n" :: "n"(NBUF - 1));
        __syncthreads();

        const float* __restrict__ buf = smem + (k & (NBUF - 1)) * IN_DIM;
        float* __restrict__ outr = out + (size_t)t * OUT_DIM;

#pragma unroll
        for (int u = 0; u < COLS_PT; u++) {
            const int j  = threadIdx.x + u * THREADS;
            const float a = buf[id[u] & 0x1FFF];
            const float b = buf[id[u] >> 13];
            // c0 + c1*a + c2*b + c3*a*b  ==  fma(b, fma(c3,a,c2), fma(c1,a,c0))
            const float p = fmaf(c[u].w, a, c[u].z);
            const float q = fmaf(c[u].y, a, c[u].x);
            outr[j] = fmaf(b, p, q);
        }
        __syncthreads();   // all threads done with buf before it is restaged
    }
}

extern "C" void kernel_launch(void* const* d_in, const int* in_sizes, int n_in,
                              void* d_out, int out_size) {
    const float* x      = (const float*)d_in[0];
    const float* weight = (const float*)d_in[1];
    const int*   idx_a  = (const int*)d_in[2];
    const int*   idx_b  = (const int*)d_in[3];
    float*       out    = (float*)d_out;

    (void)in_sizes; (void)n_in; (void)out_size;

    const int smem_bytes = NBUF * IN_DIM * (int)sizeof(float);   // 131072
    cudaFuncSetAttribute(logic_dense_kernel,
                         cudaFuncAttributeMaxDynamicSharedMemorySize,
                         smem_bytes);
    logic_dense_kernel<<<GRID, THREADS, smem_bytes>>>(x, weight, idx_a, idx_b,
                                                      out);
}